// round 4
// baseline (speedup 1.0000x reference)
#include <cuda_runtime.h>
#include <stdint.h>

// Problem constants: B=16, L=4096, H=768 (fp32)
#define B_ 16
#define L_ 4096
#define H_ 768
#define H4 (H_ / 4)            // 192 float4 lanes per row
#define TOK_PER_BLK 64         // tokens per block tile
#define CH 8                   // rows prefetched per chunk (per-thread MLP)
#define BLOCKS_PER_BATCH (L_ / TOK_PER_BLK)  // 64

// Precomputed lower bounds: bnd_g[b][v] = first p with seg[b][p] >= v, v in [0, L]
__device__ int bnd_g[B_ * (L_ + 1)];

// Kernel 1: linear-pass boundary computation (seg is sorted per batch row).
// Thread p writes bnd[v] = p for all v in (seg[p-1], seg[p]]  (seg[-1] := -1).
// Thread p == L-1 also fills the tail: bnd[v] = L for v in (seg[L-1], L].
__global__ __launch_bounds__(256)
void bounds_kernel(const int* __restrict__ seg)
{
    const int b = blockIdx.y;
    const int p = blockIdx.x * 256 + threadIdx.x;
    const int* __restrict__ segb = seg + b * L_;

    const int cur  = segb[p];
    const int prev = (p == 0) ? -1 : segb[p - 1];

    int* __restrict__ bb = bnd_g + b * (L_ + 1);
    for (int v = prev + 1; v <= cur; v++) bb[v] = p;
    if (p == L_ - 1)
        for (int v = cur + 1; v <= L_; v++) bb[v] = L_;
}

// Kernel 2: stream contiguous wordpiece rows, flush at token boundaries.
__global__ __launch_bounds__(H4, 6)
void token_segment_sum_kernel(const float* __restrict__ x,
                              float*       __restrict__ out)
{
    const int b    = blockIdx.x / BLOCKS_PER_BATCH;
    const int tile = blockIdx.x % BLOCKS_PER_BATCH;
    const int j0   = tile * TOK_PER_BLK;

    __shared__ int bnd[TOK_PER_BLK + 1];

    const int t = threadIdx.x;   // 0..191 (float4 lane)
    if (t <= TOK_PER_BLK)
        bnd[t] = bnd_g[b * (L_ + 1) + j0 + t];
    __syncthreads();

    const float4* __restrict__ xb =
        reinterpret_cast<const float4*>(x + (size_t)b * L_ * H_);
    float4* __restrict__ ob =
        reinterpret_cast<float4*>(out + (size_t)b * L_ * H_);

    const int s0 = bnd[0];
    const int s1 = bnd[TOK_PER_BLK];

    int j = 0;

    // flush tokens that are empty at the very start (bnd[j+1] == s0)
    #pragma unroll 1
    while (j < TOK_PER_BLK && bnd[j + 1] == s0) {
        __stcs(&ob[(size_t)(j0 + j) * H4 + t], make_float4(0.f, 0.f, 0.f, 0.f));
        j++;
    }

    float4 acc = make_float4(0.f, 0.f, 0.f, 0.f);

    // stream contiguous rows [s0, s1) in chunks of CH independent loads
    #pragma unroll 1
    for (int base = s0; base < s1; base += CH) {
        const int n = min(CH, s1 - base);

        float4 v[CH];
        #pragma unroll
        for (int i = 0; i < CH; i++)
            if (i < n)
                v[i] = __ldcs(&xb[(size_t)(base + i) * H4 + t]);

        #pragma unroll
        for (int i = 0; i < CH; i++) {
            if (i < n) {
                acc.x += v[i].x; acc.y += v[i].y;
                acc.z += v[i].z; acc.w += v[i].w;
                const int pos1 = base + i + 1;
                // flush every token ending exactly here (empty tokens store
                // zero since acc resets between equal boundaries)
                #pragma unroll 1
                while (j < TOK_PER_BLK && bnd[j + 1] == pos1) {
                    __stcs(&ob[(size_t)(j0 + j) * H4 + t], acc);
                    acc = make_float4(0.f, 0.f, 0.f, 0.f);
                    j++;
                }
            }
        }
    }
}

extern "C" void kernel_launch(void* const* d_in, const int* in_sizes, int n_in,
                              void* d_out, int out_size)
{
    const float* x   = (const float*)d_in[0];   // sequence_output  [B, L, H] f32
    const int*   seg = (const int*)  d_in[1];   // wordpiece_to_token [B, L] i32
    float*       out = (float*)d_out;           // [B, L, H] f32

    dim3 bgrid(L_ / 256, B_);                   // 16 x 16 blocks
    bounds_kernel<<<bgrid, 256>>>(seg);

    dim3 grid(B_ * BLOCKS_PER_BATCH);           // 1024 blocks
    dim3 block(H4);                             // 192 threads
    token_segment_sum_kernel<<<grid, block>>>(x, out);
}